// round 10
// baseline (speedup 1.0000x reference)
#include <cuda_runtime.h>
#include <cuda_fp16.h>
#include <cstdint>

#define B_ 4
#define N_ 8192
#define D_ 16
#define MIN_PTS_ 10

#define TPB 128                 // 4 warps
#define QW 32                   // queries per warp (2 x M16 blocks)
#define QCTA 128                // queries per CTA
#define CSPLIT 4                // candidate splits across grid.z
#define CPC (N_ / CSPLIT)       // 2048 candidates per CTA
#define CT 128                  // candidate tile in smem
#define CTILES (CPC / CT)       // 16
#define NT 16                   // 8-col n-subtiles per ctile
#define SCSTRIDE 12             // words per candidate row in smem (conflict-free)

__device__ int g_partial[CSPLIT][B_ * N_];

__device__ __forceinline__ float rh(float x) {          // round-to-f16 value
    return __half2float(__float2half_rn(x));
}
__device__ __forceinline__ uint32_t h2u(__half2 v) { return *reinterpret_cast<uint32_t*>(&v); }
__device__ __forceinline__ __half2 u2h(uint32_t v) { return *reinterpret_cast<__half2*>(&v); }

// D = A*B + C, f16 accumulators (packed f16x2 x2)
__device__ __forceinline__ void mma16816_f16(uint32_t& d0, uint32_t& d1,
                                             const uint32_t a[4],
                                             uint32_t b0, uint32_t b1,
                                             uint32_t c0, uint32_t c1) {
    asm volatile(
        "mma.sync.aligned.m16n8k16.row.col.f16.f16.f16.f16 "
        "{%0,%1}, {%2,%3,%4,%5}, {%6,%7}, {%8,%9};"
        : "=r"(d0), "=r"(d1)
        : "r"(a[0]), "r"(a[1]), "r"(a[2]), "r"(a[3]),
          "r"(b0), "r"(b1), "r"(c0), "r"(c1));
}

// Stage one candidate row (thread tid -> row tid) into buffer.
// Interleaved k-pair layout: row[2t] = (c[2t],c[2t+1]), row[2t+1] = (c[2t+8],c[2t+9])
// so lane tg reads (b0,b1) with ONE LDS.64 at word offset 2*tg.
__device__ __forceinline__ void stage_row(uint32_t* scu, __half2* snt, int tid,
                                          float4 v0, float4 v1, float4 v2, float4 v3) {
    float c[16] = {rh(v0.x),rh(v0.y),rh(v0.z),rh(v0.w), rh(v1.x),rh(v1.y),rh(v1.z),rh(v1.w),
                   rh(v2.x),rh(v2.y),rh(v2.z),rh(v2.w), rh(v3.x),rh(v3.y),rh(v3.z),rh(v3.w)};
    float s = 0.f;
    #pragma unroll
    for (int k = 0; k < 16; k++) s = fmaf(c[k], c[k], s);
    uint32_t* row = scu + tid * SCSTRIDE;
    #pragma unroll
    for (int t = 0; t < 4; t++) {
        row[2 * t]     = h2u(__floats2half2_rn(c[2 * t],     c[2 * t + 1]));
        row[2 * t + 1] = h2u(__floats2half2_rn(c[2 * t + 8], c[2 * t + 9]));
    }
    ((__half*)snt)[tid] = __float2half_rn(0.125f - 0.5f * s);
}

__global__ __launch_bounds__(TPB)
void dbscan_hmma_kernel(const float* __restrict__ pf) {
    __shared__ uint32_t scu[2][CT * SCSTRIDE];       // 12 KB double-buffered
    __shared__ __align__(4) __half2 snt[2][CT / 2];  // packed -t pairs (+0.125)
    __shared__ float sq[QCTA][17];                   // query staging (8.5 KB)

    const int tid   = threadIdx.x;
    const int warp  = tid >> 5;
    const int lane  = tid & 31;
    const int g     = lane >> 2;                // 0..7
    const int tg    = lane & 3;                 // 0..3
    const int b     = blockIdx.y;
    const int qbase = blockIdx.x * QCTA;
    const int cbase = blockIdx.z * CPC;
    const float* X  = pf + (size_t)b * N_ * D_;

    // ---- Stage queries (f16-rounded values) into smem ----
    for (int i = tid; i < QCTA * 4; i += TPB) {
        const int r = i >> 2, c4 = i & 3;
        float4 v = ((const float4*)(X + (size_t)(qbase + r) * D_))[c4];
        sq[r][c4 * 4 + 0] = rh(v.x); sq[r][c4 * 4 + 1] = rh(v.y);
        sq[r][c4 * 4 + 2] = rh(v.z); sq[r][c4 * 4 + 3] = rh(v.w);
    }
    __syncthreads();

    // ---- A fragments (2 row-blocks) + nh = (-0.5||q||^2) broadcast f16x2 ----
    const int r0 = warp * QW + g;               // rows r0, r0+8, r0+16, r0+24
    uint32_t alo[4], ahi[4], nhp[4];
    #pragma unroll
    for (int blk = 0; blk < 2; blk++) {
        const int ra = r0 + blk * 16, rbw = ra + 8;
        uint32_t* a = blk ? ahi : alo;
        a[0] = h2u(__floats2half2_rn(sq[ra][2 * tg],      sq[ra][2 * tg + 1]));
        a[1] = h2u(__floats2half2_rn(sq[rbw][2 * tg],     sq[rbw][2 * tg + 1]));
        a[2] = h2u(__floats2half2_rn(sq[ra][2 * tg + 8],  sq[ra][2 * tg + 9]));
        a[3] = h2u(__floats2half2_rn(sq[rbw][2 * tg + 8], sq[rbw][2 * tg + 9]));
        float s0 = 0.f, s1 = 0.f;
        #pragma unroll
        for (int k = 0; k < D_; k++) {
            s0 = fmaf(sq[ra][k], sq[ra][k], s0);
            s1 = fmaf(sq[rbw][k], sq[rbw][k], s1);
        }
        nhp[blk * 2 + 0] = h2u(__float2half2_rn(-0.5f * s0));
        nhp[blk * 2 + 1] = h2u(__float2half2_rn(-0.5f * s1));
    }

    // ---- Stage candidate tile 0 into buffer 0 ----
    {
        const float4* cr = (const float4*)(X + (size_t)(cbase + tid) * D_);
        stage_row(scu[0], snt[0], tid, cr[0], cr[1], cr[2], cr[3]);
    }
    __syncthreads();

    const __half2 zero2 = __float2half2_rn(0.0f);
    __half2 acc0 = zero2, acc1 = zero2, acc2 = zero2, acc3 = zero2;
    int p = 0;

    for (int ct = 0; ct < CTILES; ct++) {
        const bool more = (ct + 1 < CTILES);
        float4 nv0, nv1, nv2, nv3;                 // prefetch next tile (LDG early)
        if (more) {
            const float4* cr =
                (const float4*)(X + (size_t)(cbase + (ct + 1) * CT + tid) * D_);
            nv0 = cr[0]; nv1 = cr[1]; nv2 = cr[2]; nv3 = cr[3];
        }

        const uint32_t* bufc = scu[p];
        const __half2*  buft = snt[p];
        #pragma unroll
        for (int nt = 0; nt < NT; nt++) {
            const uint32_t* row = bufc + (nt * 8 + g) * SCSTRIDE;
            const uint2 bb = *(const uint2*)&row[2 * tg];        // LDS.64: b0,b1
            const __half2 ntv = buft[nt * 4 + tg];               // cols 2tg,2tg+1
            const uint32_t c0 = h2u(__hadd2(u2h(nhp[0]), ntv));
            const uint32_t c1 = h2u(__hadd2(u2h(nhp[1]), ntv));
            const uint32_t c2 = h2u(__hadd2(u2h(nhp[2]), ntv));
            const uint32_t c3 = h2u(__hadd2(u2h(nhp[3]), ntv));
            uint32_t d0, d1, d2, d3;
            mma16816_f16(d0, d1, alo, bb.x, bb.y, c0, c1);
            mma16816_f16(d2, d3, ahi, bb.x, bb.y, c2, c3);
            acc0 = __hadd2(acc0, __hgt2(u2h(d0), zero2));
            acc1 = __hadd2(acc1, __hgt2(u2h(d1), zero2));
            acc2 = __hadd2(acc2, __hgt2(u2h(d2), zero2));
            acc3 = __hadd2(acc3, __hgt2(u2h(d3), zero2));
        }

        if (more) {
            stage_row(scu[p ^ 1], snt[p ^ 1], tid, nv0, nv1, nv2, nv3);
        }
        __syncthreads();   // all warps done reading buf p and writing buf p^1
        p ^= 1;
    }

    // ---- Counts: halves are exact small ints in f16 ----
    int cnt[4];
    cnt[0] = (int)(__low2float(acc0) + __high2float(acc0));
    cnt[1] = (int)(__low2float(acc1) + __high2float(acc1));
    cnt[2] = (int)(__low2float(acc2) + __high2float(acc2));
    cnt[3] = (int)(__low2float(acc3) + __high2float(acc3));
    #pragma unroll
    for (int r = 0; r < 4; r++) {
        cnt[r] += __shfl_xor_sync(0xFFFFFFFF, cnt[r], 1);
        cnt[r] += __shfl_xor_sync(0xFFFFFFFF, cnt[r], 2);
    }
    if (tg == 0) {
        int* part = g_partial[blockIdx.z];
        #pragma unroll
        for (int r = 0; r < 4; r++)
            part[b * N_ + qbase + r0 + r * 8] = cnt[r];
    }
}

// ---------------- reduce kernel (float output: harness compares as f32) ----------------
__global__ void dbscan_reduce_kernel(float* __restrict__ out) {
    const int idx = blockIdx.x * blockDim.x + threadIdx.x;
    if (idx < B_ * N_) {
        int s = 0;
        #pragma unroll
        for (int z = 0; z < CSPLIT; z++) s += g_partial[z][idx];
        out[idx] = (s < MIN_PTS_) ? -1.0f : 0.0f;
    }
}

extern "C" void kernel_launch(void* const* d_in, const int* in_sizes, int n_in,
                              void* d_out, int out_size) {
    const float* pf = (const float*)d_in[0];
    float* out = (float*)d_out;
    (void)in_sizes; (void)n_in; (void)out_size;

    dim3 grid(N_ / QCTA, B_, CSPLIT);   // 64 x 4 x 4 = 1024 CTAs
    dbscan_hmma_kernel<<<grid, TPB>>>(pf);
    dbscan_reduce_kernel<<<(B_ * N_ + 255) / 256, 256>>>(out);
}

// round 11
// speedup vs baseline: 1.5509x; 1.5509x over previous
#include <cuda_runtime.h>
#include <cuda_fp16.h>
#include <cstdint>

#define B_ 4
#define N_ 8192
#define D_ 16
#define MIN_PTS_ 10

#define TPB 128                 // 4 warps
#define QW 32                   // queries per warp (2 x M16 blocks)
#define QCTA 128                // queries per CTA
#define CSPLIT 4                // candidate splits across grid.z
#define CPC (N_ / CSPLIT)       // 2048 candidates per CTA
#define CT 128                  // candidate tile in smem
#define CTILES (CPC / CT)       // 16
#define NT 16                   // 8-col n-subtiles per ctile
#define SCSTRIDE 12             // words per candidate row in smem (conflict-free)

__device__ int g_partial[CSPLIT][B_ * N_];

__device__ __forceinline__ float rh(float x) {          // round-to-f16 value
    return __half2float(__float2half_rn(x));
}
__device__ __forceinline__ uint32_t h2u(__half2 v) { return *reinterpret_cast<uint32_t*>(&v); }
__device__ __forceinline__ __half2 u2h(uint32_t v) { return *reinterpret_cast<__half2*>(&v); }

// D = A*B + C, f16 accumulators (packed f16x2 x2)
__device__ __forceinline__ void mma16816_f16(uint32_t& d0, uint32_t& d1,
                                             const uint32_t a[4],
                                             uint32_t b0, uint32_t b1,
                                             uint32_t c0, uint32_t c1) {
    asm volatile(
        "mma.sync.aligned.m16n8k16.row.col.f16.f16.f16.f16 "
        "{%0,%1}, {%2,%3,%4,%5}, {%6,%7}, {%8,%9};"
        : "=r"(d0), "=r"(d1)
        : "r"(a[0]), "r"(a[1]), "r"(a[2]), "r"(a[3]),
          "r"(b0), "r"(b1), "r"(c0), "r"(c1));
}

// Stage one candidate row (thread tid -> row tid). R9-proven layout:
// row[e] = (c[2e], c[2e+1]) for e=0..7; b0=row[tg], b1=row[tg+4] (all-32-bank LDS.32 pattern)
__device__ __forceinline__ void stage_row(uint32_t* scu, __half2* snt, int tid,
                                          float4 v0, float4 v1, float4 v2, float4 v3) {
    float c[16] = {rh(v0.x),rh(v0.y),rh(v0.z),rh(v0.w), rh(v1.x),rh(v1.y),rh(v1.z),rh(v1.w),
                   rh(v2.x),rh(v2.y),rh(v2.z),rh(v2.w), rh(v3.x),rh(v3.y),rh(v3.z),rh(v3.w)};
    float s = 0.f;
    #pragma unroll
    for (int k = 0; k < 16; k++) s = fmaf(c[k], c[k], s);
    uint32_t* row = scu + tid * SCSTRIDE;
    #pragma unroll
    for (int e = 0; e < 8; e++)
        row[e] = h2u(__floats2half2_rn(c[2 * e], c[2 * e + 1]));
    ((__half*)snt)[tid] = __float2half_rn(0.125f - 0.5f * s);
}

__global__ __launch_bounds__(TPB)
void dbscan_hmma_kernel(const float* __restrict__ pf) {
    __shared__ uint32_t scu[2][CT * SCSTRIDE];       // 12 KB double-buffered
    __shared__ __align__(4) __half2 snt[2][CT / 2];  // packed -t pairs (+0.125)
    __shared__ float sq[QCTA][17];                   // query staging (8.5 KB)

    const int tid   = threadIdx.x;
    const int warp  = tid >> 5;
    const int lane  = tid & 31;
    const int g     = lane >> 2;                // 0..7
    const int tg    = lane & 3;                 // 0..3
    const int b     = blockIdx.y;
    const int qbase = blockIdx.x * QCTA;
    const int cbase = blockIdx.z * CPC;
    const float* X  = pf + (size_t)b * N_ * D_;

    // ---- Stage queries (f16-rounded values) into smem ----
    for (int i = tid; i < QCTA * 4; i += TPB) {
        const int r = i >> 2, c4 = i & 3;
        float4 v = ((const float4*)(X + (size_t)(qbase + r) * D_))[c4];
        sq[r][c4 * 4 + 0] = rh(v.x); sq[r][c4 * 4 + 1] = rh(v.y);
        sq[r][c4 * 4 + 2] = rh(v.z); sq[r][c4 * 4 + 3] = rh(v.w);
    }
    __syncthreads();

    // ---- A fragments (2 row-blocks) + nh = (-0.5||q||^2) broadcast f16x2 ----
    const int r0 = warp * QW + g;               // rows r0, r0+8, r0+16, r0+24
    uint32_t alo[4], ahi[4], nhp[4];
    #pragma unroll
    for (int blk = 0; blk < 2; blk++) {
        const int ra = r0 + blk * 16, rbw = ra + 8;
        uint32_t* a = blk ? ahi : alo;
        a[0] = h2u(__floats2half2_rn(sq[ra][2 * tg],      sq[ra][2 * tg + 1]));
        a[1] = h2u(__floats2half2_rn(sq[rbw][2 * tg],     sq[rbw][2 * tg + 1]));
        a[2] = h2u(__floats2half2_rn(sq[ra][2 * tg + 8],  sq[ra][2 * tg + 9]));
        a[3] = h2u(__floats2half2_rn(sq[rbw][2 * tg + 8], sq[rbw][2 * tg + 9]));
        float s0 = 0.f, s1 = 0.f;
        #pragma unroll
        for (int k = 0; k < D_; k++) {
            s0 = fmaf(sq[ra][k], sq[ra][k], s0);
            s1 = fmaf(sq[rbw][k], sq[rbw][k], s1);
        }
        nhp[blk * 2 + 0] = h2u(__float2half2_rn(-0.5f * s0));
        nhp[blk * 2 + 1] = h2u(__float2half2_rn(-0.5f * s1));
    }

    // ---- Stage candidate tile 0 into buffer 0 ----
    {
        const float4* cr = (const float4*)(X + (size_t)(cbase + tid) * D_);
        stage_row(scu[0], snt[0], tid, cr[0], cr[1], cr[2], cr[3]);
    }
    __syncthreads();

    const __half2 zero2 = __float2half2_rn(0.0f);
    __half2 acc0 = zero2, acc1 = zero2, acc2 = zero2, acc3 = zero2;
    int p = 0;

    for (int ct = 0; ct < CTILES; ct++) {
        const bool more = (ct + 1 < CTILES);
        float4 nv0, nv1, nv2, nv3;                 // prefetch next tile (LDG early)
        if (more) {
            const float4* cr =
                (const float4*)(X + (size_t)(cbase + (ct + 1) * CT + tid) * D_);
            nv0 = cr[0]; nv1 = cr[1]; nv2 = cr[2]; nv3 = cr[3];
        }

        const uint32_t* bufc = scu[p];
        const __half2*  buft = snt[p];
        #pragma unroll 4
        for (int nt = 0; nt < NT; nt++) {
            const uint32_t* row = bufc + (nt * 8 + g) * SCSTRIDE;
            const uint32_t b0 = row[tg];
            const uint32_t b1 = row[tg + 4];
            const __half2 ntv = buft[nt * 4 + tg];      // cols 2tg, 2tg+1
            const uint32_t c0 = h2u(__hadd2(u2h(nhp[0]), ntv));
            const uint32_t c1 = h2u(__hadd2(u2h(nhp[1]), ntv));
            const uint32_t c2 = h2u(__hadd2(u2h(nhp[2]), ntv));
            const uint32_t c3 = h2u(__hadd2(u2h(nhp[3]), ntv));
            uint32_t d0, d1, d2, d3;
            mma16816_f16(d0, d1, alo, b0, b1, c0, c1);
            mma16816_f16(d2, d3, ahi, b0, b1, c2, c3);
            acc0 = __hadd2(acc0, __hgt2(u2h(d0), zero2));
            acc1 = __hadd2(acc1, __hgt2(u2h(d1), zero2));
            acc2 = __hadd2(acc2, __hgt2(u2h(d2), zero2));
            acc3 = __hadd2(acc3, __hgt2(u2h(d3), zero2));
        }

        if (more) {
            stage_row(scu[p ^ 1], snt[p ^ 1], tid, nv0, nv1, nv2, nv3);
        }
        __syncthreads();   // buf p fully read by all warps; buf p^1 staged
        p ^= 1;
    }

    // ---- Counts: halves are exact small ints in f16 ----
    int cnt[4];
    cnt[0] = (int)(__low2float(acc0) + __high2float(acc0));
    cnt[1] = (int)(__low2float(acc1) + __high2float(acc1));
    cnt[2] = (int)(__low2float(acc2) + __high2float(acc2));
    cnt[3] = (int)(__low2float(acc3) + __high2float(acc3));
    #pragma unroll
    for (int r = 0; r < 4; r++) {
        cnt[r] += __shfl_xor_sync(0xFFFFFFFF, cnt[r], 1);
        cnt[r] += __shfl_xor_sync(0xFFFFFFFF, cnt[r], 2);
    }
    if (tg == 0) {
        int* part = g_partial[blockIdx.z];
        #pragma unroll
        for (int r = 0; r < 4; r++)
            part[b * N_ + qbase + r0 + r * 8] = cnt[r];
    }
}

// ---------------- reduce kernel (float output: harness compares as f32) ----------------
__global__ void dbscan_reduce_kernel(float* __restrict__ out) {
    const int idx = blockIdx.x * blockDim.x + threadIdx.x;
    if (idx < B_ * N_) {
        int s = 0;
        #pragma unroll
        for (int z = 0; z < CSPLIT; z++) s += g_partial[z][idx];
        out[idx] = (s < MIN_PTS_) ? -1.0f : 0.0f;
    }
}

extern "C" void kernel_launch(void* const* d_in, const int* in_sizes, int n_in,
                              void* d_out, int out_size) {
    const float* pf = (const float*)d_in[0];
    float* out = (float*)d_out;
    (void)in_sizes; (void)n_in; (void)out_size;

    dim3 grid(N_ / QCTA, B_, CSPLIT);   // 64 x 4 x 4 = 1024 CTAs
    dbscan_hmma_kernel<<<grid, TPB>>>(pf);
    dbscan_reduce_kernel<<<(B_ * N_ + 255) / 256, 256>>>(out);
}